// round 3
// baseline (speedup 1.0000x reference)
#include <cuda_runtime.h>
#include <cstdint>
#include <math_constants.h>

// feat [N, C, 16, 8], scoremap [N, 13, 16, 8], conf [N, 13]
#define KP        13
#define HW        128     // 16*8 spatial
#define SP        64      // spatial pairs (f32x2 packing)
#define CPB       128     // channels per block
#define THREADS   128
#define SC_STRIDE 16      // u64 per score smem row (13 padded to 16)

// ---------- f32x2 helpers (Blackwell packed fp32) ----------
__device__ __forceinline__ unsigned long long pack2(float a, float b) {
    unsigned long long r;
    asm("mov.b64 %0, {%1, %2};" : "=l"(r) : "f"(a), "f"(b));
    return r;
}
__device__ __forceinline__ float2 unpack2(unsigned long long v) {
    float2 f;
    asm("mov.b64 {%0, %1}, %2;" : "=f"(f.x), "=f"(f.y) : "l"(v));
    return f;
}
__device__ __forceinline__ unsigned long long fma2(unsigned long long a,
                                                   unsigned long long b,
                                                   unsigned long long c) {
    unsigned long long d;
    asm("fma.rn.f32x2 %0, %1, %2, %3;" : "=l"(d) : "l"(a), "l"(b), "l"(c));
    return d;
}
__device__ __forceinline__ unsigned long long add2(unsigned long long a,
                                                   unsigned long long b) {
    unsigned long long d;
    asm("add.rn.f32x2 %0, %1, %2;" : "=l"(d) : "l"(a), "l"(b));
    return d;
}

// smem: [ score: SP x SC_STRIDE u64 (8 KB) ][ feat: SP x CPB float2 (64 KB) ]
#define SMEM_BYTES (SP * SC_STRIDE * 8 + SP * CPB * 8)

__global__ __launch_bounds__(THREADS, 3)
void horeid_kernel(const float* __restrict__ feat,
                   const float* __restrict__ score,
                   const float* __restrict__ conf,
                   float* __restrict__ out_feat,   // [N, 14, C]
                   float* __restrict__ out_conf,   // [N, 14]
                   int C)
{
    extern __shared__ unsigned char smem_raw[];
    unsigned long long* s_sc = (unsigned long long*)smem_raw;        // [SP][SC_STRIDE]
    float2* s_ft = (float2*)(smem_raw + SP * SC_STRIDE * 8);         // [SP][CPB]

    const int tid = threadIdx.x;
    const int n   = blockIdx.y;
    const int c0  = blockIdx.x * CPB;

    // ---- tiny conf normalization, one thread of blockIdx.x==0 ----
    if (blockIdx.x == 0 && tid == 0) {
        const float* cp = conf + (size_t)n * KP;
        float s = 0.0f;
        #pragma unroll
        for (int k = 0; k < KP; k++) s += fabsf(cp[k]);
        s = fmaxf(s, 1e-12f);
        float* oc = out_conf + (size_t)n * (KP + 1);
        #pragma unroll
        for (int k = 0; k < KP; k++) oc[k] = cp[k] / s;
        oc[KP] = 1.0f;
    }

    // ---- stage scoremap[n]: s_sc[sp][k ^ 2*(sp&7)] = (score[k][2sp], score[k][2sp+1]) ----
    // even XOR mask keeps (2j,2j+1) pairs adjacent & 16B-aligned for LDS.128 reads,
    // and breaks the all-lanes-same-bank pattern of the k-major staging stores.
    const float2* g_sc = (const float2*)(score + (size_t)n * KP * HW);
    for (int i = tid; i < KP * SP; i += THREADS) {
        int k  = i >> 6;          // 0..12
        int sp = i & 63;
        float2 v = g_sc[i];       // = g_sc[k*SP + sp]
        s_sc[sp * SC_STRIDE + (k ^ (2 * (sp & 7)))] = pack2(v.x, v.y);
    }

    // ---- stage feat tile [CPB x HW] -> transposed [spatial-pair][c], XOR swizzle ----
    // row r holds (feat[c][2r], feat[c][2r+1]); physical col = c ^ ((r>>1)&31).
    const float4* g4 = (const float4*)(feat + ((size_t)n * C + c0) * HW);
    #pragma unroll
    for (int i = 0; i < (CPB * HW / 4) / THREADS; i++) {     // 32 iters
        int idx = tid + i * THREADS;
        int cc  = idx >> 5;        // channel within tile
        int sq  = idx & 31;        // float4 index within row
        float4 v = g4[(size_t)cc * (HW / 4) + sq];
        int col = cc ^ sq;         // mask for rows 2sq, 2sq+1 is sq
        s_ft[(2 * sq    ) * CPB + col] = make_float2(v.x, v.y);
        s_ft[(2 * sq + 1) * CPB + col] = make_float2(v.z, v.w);
    }
    __syncthreads();

    // ---- main accumulation: one channel per thread ----
    unsigned long long acc[KP];
    #pragma unroll
    for (int k = 0; k < KP; k++) acc[k] = 0ull;
    unsigned long long sum2 = 0ull;
    float mx = -CUDART_INF_F;

    const ulonglong2* s_sc2 = (const ulonglong2*)s_sc;   // [SP][SC_STRIDE/2]

    #pragma unroll 4
    for (int sp = 0; sp < SP; sp++) {
        const int m = sp & 7;
        float2 f = s_ft[sp * CPB + (tid ^ ((sp >> 1) & 31))];
        unsigned long long fd = pack2(f.x, f.y);

        const ulonglong2* srow = s_sc2 + sp * (SC_STRIDE / 2);
        #pragma unroll
        for (int j = 0; j < 6; j++) {                     // k = 2j, 2j+1
            ulonglong2 q = srow[j ^ m];                   // one LDS.128 broadcast
            acc[2 * j    ] = fma2(fd, q.x, acc[2 * j    ]);
            acc[2 * j + 1] = fma2(fd, q.y, acc[2 * j + 1]);
        }
        unsigned long long q12 = s_sc[sp * SC_STRIDE + (12 ^ (2 * m))];
        acc[12] = fma2(fd, q12, acc[12]);

        sum2 = add2(sum2, fd);
        mx = fmaxf(mx, fmaxf(f.x, f.y));
    }

    // ---- epilogue ----
    float2 s = unpack2(sum2);
    float g = (s.x + s.y) * (1.0f / (float)HW) + mx;
    float* op = out_feat + ((size_t)n * (KP + 1)) * C + c0 + tid;
    #pragma unroll
    for (int k = 0; k < KP; k++) {
        float2 a = unpack2(acc[k]);
        op[(size_t)k * C] = a.x + a.y;
    }
    op[(size_t)KP * C] = g;
}

extern "C" void kernel_launch(void* const* d_in, const int* in_sizes, int n_in,
                              void* d_out, int out_size)
{
    const float* feat  = (const float*)d_in[0];
    const float* score = (const float*)d_in[1];
    const float* conf  = (const float*)d_in[2];
    float* out = (float*)d_out;

    const int N = in_sizes[2] / KP;                 // 256
    const int C = in_sizes[0] / ((size_t)N * HW);   // 2048

    float* out_feat = out;
    float* out_conf = out + (size_t)N * (KP + 1) * C;

    cudaFuncSetAttribute(horeid_kernel,
                         cudaFuncAttributeMaxDynamicSharedMemorySize, SMEM_BYTES);

    dim3 grid(C / CPB, N);
    horeid_kernel<<<grid, THREADS, SMEM_BYTES>>>(feat, score, conf,
                                                 out_feat, out_conf, C);
}

// round 4
// speedup vs baseline: 1.5024x; 1.5024x over previous
#include <cuda_runtime.h>
#include <cstdint>
#include <math_constants.h>

// feat [N, C, 16, 8], scoremap [N, 13, 16, 8], conf [N, 13]
#define KP        13
#define HW        128       // 16*8 spatial
#define SPT       64        // total spatial pairs (f32x2 packing)
#define CPB       256       // channels per block (2 per thread)
#define THREADS   128
#define SPC       16        // spatial pairs per chunk
#define NCHUNK    (SPT / SPC)
#define FSTRIDE   (CPB + 1) // float2 per feat smem row (pad -> 2-phase reads)
#define SCS       18        // u64 per score smem row (13 pad to 18: 144B, 16B-aligned)

// ---------- f32x2 helpers (Blackwell packed fp32) ----------
__device__ __forceinline__ unsigned long long pack2(float a, float b) {
    unsigned long long r;
    asm("mov.b64 %0, {%1, %2};" : "=l"(r) : "f"(a), "f"(b));
    return r;
}
__device__ __forceinline__ float2 unpack2(unsigned long long v) {
    float2 f;
    asm("mov.b64 {%0, %1}, %2;" : "=f"(f.x), "=f"(f.y) : "l"(v));
    return f;
}
__device__ __forceinline__ unsigned long long fma2(unsigned long long a,
                                                   unsigned long long b,
                                                   unsigned long long c) {
    unsigned long long d;
    asm("fma.rn.f32x2 %0, %1, %2, %3;" : "=l"(d) : "l"(a), "l"(b), "l"(c));
    return d;
}
__device__ __forceinline__ unsigned long long add2(unsigned long long a,
                                                   unsigned long long b) {
    unsigned long long d;
    asm("add.rn.f32x2 %0, %1, %2;" : "=l"(d) : "l"(a), "l"(b));
    return d;
}

// smem: [ score: SPT x SCS u64 = 9216 B ][ feat: SPC x FSTRIDE float2 = 32896 B ]
#define SMEM_BYTES (SPT * SCS * 8 + SPC * FSTRIDE * 8)

__global__ __launch_bounds__(THREADS, 4)
void horeid_kernel(const float* __restrict__ feat,
                   const float* __restrict__ score,
                   const float* __restrict__ conf,
                   float* __restrict__ out_feat,   // [N, 14, C]
                   float* __restrict__ out_conf,   // [N, 14]
                   int C)
{
    extern __shared__ unsigned char smem_raw[];
    unsigned long long* s_sc = (unsigned long long*)smem_raw;       // [SPT][SCS]
    float2* s_ft = (float2*)(smem_raw + SPT * SCS * 8);             // [SPC][FSTRIDE]

    const int tid = threadIdx.x;
    const int n   = blockIdx.y;
    const int c0  = blockIdx.x * CPB;

    // ---- tiny conf normalization, one thread of blockIdx.x==0 ----
    if (blockIdx.x == 0 && tid == 0) {
        const float* cp = conf + (size_t)n * KP;
        float s = 0.0f;
        #pragma unroll
        for (int k = 0; k < KP; k++) s += fabsf(cp[k]);
        s = fmaxf(s, 1e-12f);
        float* oc = out_conf + (size_t)n * (KP + 1);
        #pragma unroll
        for (int k = 0; k < KP; k++) oc[k] = cp[k] / s;
        oc[KP] = 1.0f;
    }

    // ---- stage all scoremap[n] once: s_sc[sp][k] = (score[k][2sp], score[k][2sp+1]) ----
    const float2* g_sc = (const float2*)(score + (size_t)n * KP * HW);
    #pragma unroll
    for (int i = tid; i < KP * SPT; i += THREADS) {
        int k  = i >> 6;          // 0..12
        int sp = i & 63;
        float2 v = g_sc[i];
        s_sc[sp * SCS + k] = pack2(v.x, v.y);
    }

    // ---- accumulators for 2 channels: cA = c0+tid, cB = cA+128 ----
    unsigned long long accA[KP], accB[KP];
    #pragma unroll
    for (int k = 0; k < KP; k++) { accA[k] = 0ull; accB[k] = 0ull; }
    unsigned long long sumA = 0ull, sumB = 0ull;
    float2 mxA = make_float2(-CUDART_INF_F, -CUDART_INF_F);
    float2 mxB = make_float2(-CUDART_INF_F, -CUDART_INF_F);

    const float4* g4 = (const float4*)(feat + ((size_t)n * C + c0) * HW);

    for (int ch = 0; ch < NCHUNK; ch++) {
        if (ch) __syncthreads();   // prev chunk fully consumed before overwrite

        // ---- stage feat chunk: 256 ch x 32 spatial -> transposed [sp-pair][c] ----
        // idx: cc = idx>>3 (channel), sqL = idx&7 (local float4 within chunk)
        #pragma unroll 4
        for (int it = 0; it < (CPB * 2 * SPC / 4) / THREADS; it++) {  // 16 iters
            int idx = tid + it * THREADS;
            int cc  = idx >> 3;
            int sqL = idx & 7;
            float4 v = g4[(size_t)cc * (HW / 4) + (ch * (SPC / 2) + sqL)];
            s_ft[(2 * sqL    ) * FSTRIDE + cc] = make_float2(v.x, v.y);
            s_ft[(2 * sqL + 1) * FSTRIDE + cc] = make_float2(v.z, v.w);
        }
        __syncthreads();

        // ---- compute chunk: immediate smem offsets, no address ALU ----
        const unsigned long long* scb = s_sc + ch * SPC * SCS;
        #pragma unroll 8
        for (int spL = 0; spL < SPC; spL++) {
            float2 fa = s_ft[spL * FSTRIDE + tid];
            float2 fb = s_ft[spL * FSTRIDE + tid + (CPB / 2)];
            unsigned long long fda = pack2(fa.x, fa.y);
            unsigned long long fdb = pack2(fb.x, fb.y);

            const ulonglong2* srow = (const ulonglong2*)(scb + spL * SCS);
            #pragma unroll
            for (int j = 0; j < 6; j++) {              // k = 2j, 2j+1 via LDS.128
                ulonglong2 q = srow[j];
                accA[2 * j    ] = fma2(fda, q.x, accA[2 * j    ]);
                accB[2 * j    ] = fma2(fdb, q.x, accB[2 * j    ]);
                accA[2 * j + 1] = fma2(fda, q.y, accA[2 * j + 1]);
                accB[2 * j + 1] = fma2(fdb, q.y, accB[2 * j + 1]);
            }
            unsigned long long q12 = scb[spL * SCS + 12];
            accA[12] = fma2(fda, q12, accA[12]);
            accB[12] = fma2(fdb, q12, accB[12]);

            sumA = add2(sumA, fda);
            sumB = add2(sumB, fdb);
            mxA.x = fmaxf(mxA.x, fa.x); mxA.y = fmaxf(mxA.y, fa.y);
            mxB.x = fmaxf(mxB.x, fb.x); mxB.y = fmaxf(mxB.y, fb.y);
        }
    }

    // ---- epilogue: 13 local sums + (mean + max) global, for both channels ----
    const int cA = c0 + tid;
    const int cB = cA + (CPB / 2);
    float* op = out_feat + (size_t)n * (KP + 1) * C;
    #pragma unroll
    for (int k = 0; k < KP; k++) {
        float2 a = unpack2(accA[k]);
        float2 b = unpack2(accB[k]);
        op[(size_t)k * C + cA] = a.x + a.y;
        op[(size_t)k * C + cB] = b.x + b.y;
    }
    float2 sa = unpack2(sumA), sb = unpack2(sumB);
    op[(size_t)KP * C + cA] = (sa.x + sa.y) * (1.0f / (float)HW) + fmaxf(mxA.x, mxA.y);
    op[(size_t)KP * C + cB] = (sb.x + sb.y) * (1.0f / (float)HW) + fmaxf(mxB.x, mxB.y);
}

extern "C" void kernel_launch(void* const* d_in, const int* in_sizes, int n_in,
                              void* d_out, int out_size)
{
    const float* feat  = (const float*)d_in[0];
    const float* score = (const float*)d_in[1];
    const float* conf  = (const float*)d_in[2];
    float* out = (float*)d_out;

    const int N = in_sizes[2] / KP;                 // 256
    const int C = in_sizes[0] / ((size_t)N * HW);   // 2048

    float* out_feat = out;
    float* out_conf = out + (size_t)N * (KP + 1) * C;

    cudaFuncSetAttribute(horeid_kernel,
                         cudaFuncAttributeMaxDynamicSharedMemorySize, SMEM_BYTES);

    dim3 grid(C / CPB, N);
    horeid_kernel<<<grid, THREADS, SMEM_BYTES>>>(feat, score, conf,
                                                 out_feat, out_conf, C);
}